// round 11
// baseline (speedup 1.0000x reference)
#include <cuda_runtime.h>

#define Bb 4
#define Tt 12
#define Nn 512
#define Dd 128
#define Ll 4
#define Hh 64

typedef unsigned long long ull;

// ---------------- scratch (no allocation allowed) ----------------
__device__ float g_src[Bb * Nn * Dd];        // src_proj
__device__ float g_tgt[Bb * Nn * Dd];        // tgt_proj + bs1 folded in
__device__ float g_adj[Bb * Nn * Nn];        // thresholded adjacency
__device__ float g_p[4][Bb * Nn * Nn];       // a2 partials (k-quarters); p[0] becomes full sum
__device__ float g_q[4][Bb * Nn * Nn];       // a3 partials
__device__ unsigned g_maxbits[Bb];           // per-batch max (float bits, all >= 0)

// ---------------- stage 1: lag encoders + mean + projections ----------------
__global__ __launch_bounds__(256) void k_encode(
    const float* __restrict__ x,
    const float* __restrict__ W1, const float* __restrict__ b1,
    const float* __restrict__ W2, const float* __restrict__ b2,
    const float* __restrict__ Ws1, const float* __restrict__ bs1)
{
    __shared__ float xl[16 * 512];   // [(r*4+l)*128 + d]; later reused as agg[r*128+d]
    __shared__ float hs[16 * 256];   // [r*256 + l*64 + j]

    int tid = threadIdx.x;
    if (blockIdx.x == 0 && tid < Bb) g_maxbits[tid] = 0u;   // folded k_init

    int bn0 = blockIdx.x * 16;           // first global row (b*N + n)
    int b   = bn0 >> 9;
    int n0  = bn0 & (Nn - 1);

    #pragma unroll
    for (int i = 0; i < 32; i++) {
        int e  = tid + i * 256;
        int d  = e & 127;
        int rl = e >> 7;
        int r  = rl >> 2, l = rl & 3;
        xl[e] = x[(((b * Tt) + (Tt - 1 - l)) * Nn + (n0 + r)) * Dd + d];
    }
    __syncthreads();

    {
        int l = tid >> 6, j = tid & 63;
        float acc[16];
        float bb = b1[l * Hh + j];
        #pragma unroll
        for (int r = 0; r < 16; r++) acc[r] = bb;
        const float* w1 = W1 + (size_t)l * Dd * Hh + j;
        for (int d = 0; d < Dd; d++) {
            float w = w1[d * Hh];
            #pragma unroll
            for (int r = 0; r < 16; r++)
                acc[r] = fmaf(xl[(r * 4 + l) * 128 + d], w, acc[r]);
        }
        #pragma unroll
        for (int r = 0; r < 16; r++)
            hs[r * 256 + tid] = fmaxf(acc[r], 0.f);
    }
    __syncthreads();

    {
        int d = tid & 127, halfr = tid >> 7;
        float bbar = 0.f;
        #pragma unroll
        for (int l = 0; l < Ll; l++) bbar += b2[l * Dd + d];
        bbar *= 0.25f;
        float acc[8];
        #pragma unroll
        for (int r = 0; r < 8; r++) acc[r] = 0.f;
        for (int o = 0; o < Ll * Hh; o++) {
            float w = W2[(size_t)o * Dd + d];
            #pragma unroll
            for (int r = 0; r < 8; r++)
                acc[r] = fmaf(hs[(halfr * 8 + r) * 256 + o], w, acc[r]);
        }
        #pragma unroll
        for (int r = 0; r < 8; r++)
            xl[(halfr * 8 + r) * 128 + d] = fmaf(acc[r], 0.25f, bbar);
    }
    __syncthreads();

    {
        int dcol = tid & 127;
        int half = tid >> 7;                 // 0 = src, 1 = tgt
        float acc[16];
        float binit = half ? bs1[dcol] : 0.f;
        #pragma unroll
        for (int r = 0; r < 16; r++) acc[r] = binit;
        const float* ws = Ws1 + (size_t)half * Dd * Dd + dcol;
        for (int dd = 0; dd < Dd; dd++) {
            float w = ws[dd * Dd];
            #pragma unroll
            for (int r = 0; r < 16; r++)
                acc[r] = fmaf(xl[r * 128 + dd], w, acc[r]);
        }
        float* dst = half ? g_tgt : g_src;
        #pragma unroll
        for (int r = 0; r < 16; r++)
            dst[(size_t)(bn0 + r) * Dd + dcol] = acc[r];
    }
}

// ---------------- stage 2: pairwise scorer (packed f32x2) ----------------
__device__ __forceinline__ ull pk2(float x) {
    ull r;
    asm("mov.b64 %0, {%1, %1};" : "=l"(r) : "f"(x));
    return r;
}

__device__ __forceinline__ void pstep(ull& acc, ull t2, ull s2, ull w2) {
    asm("{\n\t"
        ".reg .b64 t;\n\t"
        ".reg .f32 lo, hi;\n\t"
        "add.rn.f32x2 t, %1, %2;\n\t"
        "mov.b64 {lo, hi}, t;\n\t"
        "max.f32 lo, lo, 0f00000000;\n\t"
        "max.f32 hi, hi, 0f00000000;\n\t"
        "mov.b64 t, {lo, hi};\n\t"
        "fma.rn.f32x2 %0, t, %3, %0;\n\t"
        "}"
        : "+l"(acc) : "l"(t2), "l"(s2), "l"(w2));
}

__global__ __launch_bounds__(128) void k_score(
    const float* __restrict__ Ws2, const float* __restrict__ bs2)
{
    __shared__ float st [32][132];   // [i][d]
    __shared__ float ttT[128][36];   // [d][j]
    __shared__ float w4[128];

    int b  = blockIdx.z;
    int i0 = blockIdx.y * 32, j0 = blockIdx.x * 32;
    int tx = threadIdx.x, ty = threadIdx.y;
    int tid = ty * 4 + tx;

    #pragma unroll
    for (int it = 0; it < 8; it++) {
        int e = tid + it * 128;
        int r = e >> 5, c4 = (e & 31) * 4;
        *(float4*)&st[r][c4] =
            *(const float4*)&g_src[(size_t)(b * Nn + i0 + r) * Dd + c4];
    }
    #pragma unroll
    for (int it = 0; it < 2; it++) {
        int e  = tid + it * 128;
        int j4 = (e & 7) * 4, d4 = (e >> 3) * 4;
        const float* base = g_tgt + (size_t)(b * Nn + j0 + j4) * Dd + d4;
        float4 r0 = *(const float4*)(base);
        float4 r1 = *(const float4*)(base + Dd);
        float4 r2 = *(const float4*)(base + 2 * Dd);
        float4 r3 = *(const float4*)(base + 3 * Dd);
        *(float4*)&ttT[d4 + 0][j4] = make_float4(r0.x, r1.x, r2.x, r3.x);
        *(float4*)&ttT[d4 + 1][j4] = make_float4(r0.y, r1.y, r2.y, r3.y);
        *(float4*)&ttT[d4 + 2][j4] = make_float4(r0.z, r1.z, r2.z, r3.z);
        *(float4*)&ttT[d4 + 3][j4] = make_float4(r0.w, r1.w, r2.w, r3.w);
    }
    w4[tid] = Ws2[tid];
    __syncthreads();

    int ti = ty;
    int jb = tx * 8;
    ull acc01 = 0, acc23 = 0, acc45 = 0, acc67 = 0;

    #pragma unroll 4
    for (int d = 0; d < Dd; d += 4) {
        float4 sv = *(const float4*)&st[ti][d];
        float4 wv = *(const float4*)&w4[d];
        float svv[4] = {sv.x, sv.y, sv.z, sv.w};
        float wvv[4] = {wv.x, wv.y, wv.z, wv.w};
        #pragma unroll
        for (int q = 0; q < 4; q++) {
            ulonglong2 ta = *(const ulonglong2*)&ttT[d + q][jb];
            ulonglong2 tb = *(const ulonglong2*)&ttT[d + q][jb + 4];
            ull s2 = pk2(svv[q]);
            ull w2 = pk2(wvv[q]);
            pstep(acc01, ta.x, s2, w2);
            pstep(acc23, ta.y, s2, w2);
            pstep(acc45, tb.x, s2, w2);
            pstep(acc67, tb.y, s2, w2);
        }
    }

    float a[8];
    asm("mov.b64 {%0, %1}, %2;" : "=f"(a[0]), "=f"(a[1]) : "l"(acc01));
    asm("mov.b64 {%0, %1}, %2;" : "=f"(a[2]), "=f"(a[3]) : "l"(acc23));
    asm("mov.b64 {%0, %1}, %2;" : "=f"(a[4]), "=f"(a[5]) : "l"(acc45));
    asm("mov.b64 {%0, %1}, %2;" : "=f"(a[6]), "=f"(a[7]) : "l"(acc67));

    float bz = bs2[0];
    int i = i0 + ti;
    float o[8];
    #pragma unroll
    for (int jj = 0; jj < 8; jj++) {
        int j = j0 + jb + jj;
        float sc = 1.f / (1.f + __expf(-(a[jj] + bz)));
        o[jj] = (sc > 0.1f && i != j) ? sc : 0.f;
    }
    float* dst = g_adj + ((size_t)b * Nn + i) * Nn + j0 + jb;
    *(float4*)(dst)     = make_float4(o[0], o[1], o[2], o[3]);
    *(float4*)(dst + 4) = make_float4(o[4], o[5], o[6], o[7]);
}

// ---------------- stage 3/4: TF32 GEMMs, split-K=4, register double-buffer --
// PHASE=0: p[kq] = adj[:, kslice] @ adj[kslice, :]
// PHASE=1: q[kq] = psum[:, kslice] @ adj[kslice, :]   (psum staged in p[0])
#define TM 64
#define TN 64
#define TK 32
#define KH 128          // K per split quarter
#define ASTR 36
#define BSTR 72

__device__ __forceinline__ void mma_tf32(float* d, const unsigned* a,
                                         const unsigned* b, const float* c) {
    asm volatile(
        "mma.sync.aligned.m16n8k8.row.col.f32.tf32.tf32.f32 "
        "{%0,%1,%2,%3}, {%4,%5,%6,%7}, {%8,%9}, {%10,%11,%12,%13};\n"
        : "=f"(d[0]), "=f"(d[1]), "=f"(d[2]), "=f"(d[3])
        : "r"(a[0]), "r"(a[1]), "r"(a[2]), "r"(a[3]),
          "r"(b[0]), "r"(b[1]),
          "f"(c[0]), "f"(c[1]), "f"(c[2]), "f"(c[3]));
}

template <int PHASE>
__global__ __launch_bounds__(128) void k_mma()
{
    int z  = blockIdx.z;
    int b  = z >> 2;
    int kq = z & 3;
    int kbase = kq * KH;

    const float* A1 = (PHASE ? g_p[0] : g_adj) + (size_t)b * Nn * Nn;
    const float* Bp = g_adj + (size_t)b * Nn * Nn;
    float* Ob = (PHASE ? g_q[kq] : g_p[kq]) + (size_t)b * Nn * Nn;

    __shared__ float As[2][TM * ASTR];
    __shared__ float Bs[2][TK * BSTR];

    int tid  = threadIdx.x;
    int m0   = blockIdx.y * TM, n0 = blockIdx.x * TN;
    int warpId = tid >> 5, lane = tid & 31;
    int wm  = (warpId & 1) * 32;
    int wn  = (warpId >> 1) * 32;
    int gid = lane >> 2, tig = lane & 3;

    int arow = tid >> 3, ac4 = (tid & 7) * 4;     // A rows arow + p*16
    int brow = tid >> 4, bc4 = (tid & 15) * 4;    // B rows brow + p*8

    const float* agp = A1 + (size_t)(m0 + arow) * Nn + kbase + ac4;
    const float* bgp = Bp + (size_t)(kbase + brow) * Nn + n0 + bc4;

    float4 ra[4], rb[4];
    #pragma unroll
    for (int p = 0; p < 4; p++) {
        ra[p] = *(const float4*)(agp + (size_t)p * 16 * Nn);
        rb[p] = *(const float4*)(bgp + (size_t)p * 8 * Nn);
    }
    #pragma unroll
    for (int p = 0; p < 4; p++) {
        *(float4*)(As[0] + (arow + p * 16) * ASTR + ac4) = ra[p];
        *(float4*)(Bs[0] + (brow + p * 8) * BSTR + bc4)  = rb[p];
    }
    __syncthreads();

    float acc[2][4][4];
    #pragma unroll
    for (int i = 0; i < 2; i++)
        #pragma unroll
        for (int j = 0; j < 4; j++)
            #pragma unroll
            for (int r = 0; r < 4; r++) acc[i][j][r] = 0.f;

    const int NT = KH / TK;
    #pragma unroll 1
    for (int kt = 0; kt < NT; kt++) {
        int cur = kt & 1;
        if (kt + 1 < NT) {                        // prefetch next panel
            int k0 = (kt + 1) * TK;
            #pragma unroll
            for (int p = 0; p < 4; p++) {
                ra[p] = *(const float4*)(agp + k0 + (size_t)p * 16 * Nn);
                rb[p] = *(const float4*)(bgp + (size_t)k0 * Nn + (size_t)p * 8 * Nn);
            }
        }

        const float* Ac = As[cur];
        const float* Bc = Bs[cur];
        #pragma unroll
        for (int ks = 0; ks < 4; ks++) {
            int kb = ks * 8;
            unsigned af[2][4], bf[4][2];
            #pragma unroll
            for (int mt = 0; mt < 2; mt++) {
                int r0 = wm + mt * 16 + gid;
                af[mt][0] = __float_as_uint(Ac[r0 * ASTR + kb + tig]);
                af[mt][1] = __float_as_uint(Ac[(r0 + 8) * ASTR + kb + tig]);
                af[mt][2] = __float_as_uint(Ac[r0 * ASTR + kb + tig + 4]);
                af[mt][3] = __float_as_uint(Ac[(r0 + 8) * ASTR + kb + tig + 4]);
            }
            #pragma unroll
            for (int nt = 0; nt < 4; nt++) {
                int c0 = wn + nt * 8 + gid;
                bf[nt][0] = __float_as_uint(Bc[(kb + tig) * BSTR + c0]);
                bf[nt][1] = __float_as_uint(Bc[(kb + tig + 4) * BSTR + c0]);
            }
            #pragma unroll
            for (int mt = 0; mt < 2; mt++)
                #pragma unroll
                for (int nt = 0; nt < 4; nt++)
                    mma_tf32(acc[mt][nt], af[mt], bf[nt], acc[mt][nt]);
        }

        if (kt + 1 < NT) {
            int nxt = cur ^ 1;
            #pragma unroll
            for (int p = 0; p < 4; p++) {
                *(float4*)(As[nxt] + (arow + p * 16) * ASTR + ac4) = ra[p];
                *(float4*)(Bs[nxt] + (brow + p * 8) * BSTR + bc4)  = rb[p];
            }
        }
        __syncthreads();
    }

    #pragma unroll
    for (int mt = 0; mt < 2; mt++) {
        #pragma unroll
        for (int nt = 0; nt < 4; nt++) {
            int row = m0 + wm + mt * 16 + gid;
            int col = n0 + wn + nt * 8 + 2 * tig;
            #pragma unroll
            for (int h = 0; h < 2; h++) {
                int r = row + h * 8;
                *(float2*)(Ob + (size_t)r * Nn + col) =
                    make_float2(acc[mt][nt][2 * h + 0], acc[mt][nt][2 * h + 1]);
            }
        }
    }
}

// ---------------- stage 3.5: p[0] += p[1] + p[2] + p[3] ----------------
__global__ __launch_bounds__(256) void k_sum()
{
    int idx = blockIdx.x * 256 + threadIdx.x;     // over B*N*N/4 float4
    float4 a = ((const float4*)g_p[0])[idx];
    float4 c = ((const float4*)g_p[1])[idx];
    float4 d = ((const float4*)g_p[2])[idx];
    float4 e = ((const float4*)g_p[3])[idx];
    a.x += c.x + d.x + e.x;
    a.y += c.y + d.y + e.y;
    a.z += c.z + d.z + e.z;
    a.w += c.w + d.w + e.w;
    ((float4*)g_p[0])[idx] = a;
}

// ---------------- stage 5: combine + per-batch max ----------------
__global__ __launch_bounds__(256) void k_enhance(float* __restrict__ out)
{
    __shared__ float wmax[8];
    int idx = blockIdx.x * 256 + threadIdx.x;     // over B*N*N/4 float4
    int b = idx >> 16;

    float4 a  = ((const float4*)g_adj)[idx];
    float4 p  = ((const float4*)g_p[0])[idx];     // already summed
    float4 q0 = ((const float4*)g_q[0])[idx];
    float4 q1 = ((const float4*)g_q[1])[idx];
    float4 q2 = ((const float4*)g_q[2])[idx];
    float4 q3 = ((const float4*)g_q[3])[idx];

    float4 e;
    e.x = a.x + 0.5f * p.x + 0.25f * (q0.x + q1.x + q2.x + q3.x);
    e.y = a.y + 0.5f * p.y + 0.25f * (q0.y + q1.y + q2.y + q3.y);
    e.z = a.z + 0.5f * p.z + 0.25f * (q0.z + q1.z + q2.z + q3.z);
    e.w = a.w + 0.5f * p.w + 0.25f * (q0.w + q1.w + q2.w + q3.w);
    ((float4*)out)[idx] = e;

    float lmax = fmaxf(fmaxf(e.x, e.y), fmaxf(e.z, e.w));
    #pragma unroll
    for (int s = 16; s > 0; s >>= 1)
        lmax = fmaxf(lmax, __shfl_xor_sync(0xFFFFFFFFu, lmax, s));
    int warpId = threadIdx.x >> 5, lane = threadIdx.x & 31;
    if (lane == 0) wmax[warpId] = lmax;
    __syncthreads();
    if (threadIdx.x == 0) {
        float m = wmax[0];
        #pragma unroll
        for (int i = 1; i < 8; i++) m = fmaxf(m, wmax[i]);
        atomicMax(&g_maxbits[b], __float_as_uint(m));
    }
}

// ---------------- stage 6: normalize (float4) ----------------
__global__ void k_norm(float* __restrict__ out)
{
    int idx = blockIdx.x * 256 + threadIdx.x;
    int b = idx >> 16;
    float mx = __uint_as_float(g_maxbits[b]);
    float inv = 1.f / (mx + 1e-8f);
    float4 v = ((const float4*)out)[idx];
    v.x *= inv; v.y *= inv; v.z *= inv; v.w *= inv;
    ((float4*)out)[idx] = v;
}

// ---------------- launch ----------------
extern "C" void kernel_launch(void* const* d_in, const int* in_sizes, int n_in,
                              void* d_out, int out_size)
{
    const float* x   = (const float*)d_in[0];
    const float* W1  = (const float*)d_in[1];
    const float* b1  = (const float*)d_in[2];
    const float* W2  = (const float*)d_in[3];
    const float* b2  = (const float*)d_in[4];
    const float* Ws1 = (const float*)d_in[5];
    const float* bs1 = (const float*)d_in[6];
    const float* Ws2 = (const float*)d_in[7];
    const float* bs2 = (const float*)d_in[8];
    float* out = (float*)d_out;

    k_encode<<<(Bb * Nn) / 16, 256>>>(x, W1, b1, W2, b2, Ws1, bs1);
    k_score<<<dim3(Nn / 32, Nn / 32, Bb), dim3(4, 32)>>>(Ws2, bs2);
    k_mma<0><<<dim3(Nn / TN, Nn / TM, Bb * 4), 128>>>();
    k_sum<<<(Bb * Nn * Nn) / 1024, 256>>>();
    k_mma<1><<<dim3(Nn / TN, Nn / TM, Bb * 4), 128>>>();
    k_enhance<<<(Bb * Nn * Nn) / 1024, 256>>>(out);
    k_norm<<<(Bb * Nn * Nn) / 1024, 256>>>(out);
}

// round 12
// speedup vs baseline: 1.0204x; 1.0204x over previous
#include <cuda_runtime.h>

#define Bb 4
#define Tt 12
#define Nn 512
#define Dd 128
#define Ll 4
#define Hh 64

typedef unsigned long long ull;

// ---------------- scratch (no allocation allowed) ----------------
__device__ float g_src[Bb * Nn * Dd];     // src_proj
__device__ float g_tgt[Bb * Nn * Dd];     // tgt_proj + bs1 folded in
__device__ float g_adj[Bb * Nn * Nn];     // thresholded adjacency
__device__ float g_p0[Bb * Nn * Nn];      // a2 partial (k-half 0)
__device__ float g_p1[Bb * Nn * Nn];      // a2 partial (k-half 1)
__device__ float g_q0[Bb * Nn * Nn];      // a3 partial (k-half 0)
__device__ float g_q1[Bb * Nn * Nn];      // a3 partial (k-half 1)
__device__ unsigned g_maxbits[Bb];        // per-batch max (float bits, all >= 0)

// ---------------- stage 1: lag encoders + mean + projections ----------------
__global__ __launch_bounds__(256) void k_encode(
    const float* __restrict__ x,
    const float* __restrict__ W1, const float* __restrict__ b1,
    const float* __restrict__ W2, const float* __restrict__ b2,
    const float* __restrict__ Ws1, const float* __restrict__ bs1)
{
    __shared__ float xl[16 * 512];   // [(r*4+l)*128 + d]; later reused as agg[r*128+d]
    __shared__ float hs[16 * 256];   // [r*256 + l*64 + j]

    int tid = threadIdx.x;
    if (blockIdx.x == 0 && tid < Bb) g_maxbits[tid] = 0u;   // folded k_init

    int bn0 = blockIdx.x * 16;           // first global row (b*N + n)
    int b   = bn0 >> 9;
    int n0  = bn0 & (Nn - 1);

    #pragma unroll
    for (int i = 0; i < 32; i++) {
        int e  = tid + i * 256;
        int d  = e & 127;
        int rl = e >> 7;
        int r  = rl >> 2, l = rl & 3;
        xl[e] = x[(((b * Tt) + (Tt - 1 - l)) * Nn + (n0 + r)) * Dd + d];
    }
    __syncthreads();

    {
        int l = tid >> 6, j = tid & 63;
        float acc[16];
        float bb = b1[l * Hh + j];
        #pragma unroll
        for (int r = 0; r < 16; r++) acc[r] = bb;
        const float* w1 = W1 + (size_t)l * Dd * Hh + j;
        for (int d = 0; d < Dd; d++) {
            float w = w1[d * Hh];
            #pragma unroll
            for (int r = 0; r < 16; r++)
                acc[r] = fmaf(xl[(r * 4 + l) * 128 + d], w, acc[r]);
        }
        #pragma unroll
        for (int r = 0; r < 16; r++)
            hs[r * 256 + tid] = fmaxf(acc[r], 0.f);
    }
    __syncthreads();

    {
        int d = tid & 127, halfr = tid >> 7;
        float bbar = 0.f;
        #pragma unroll
        for (int l = 0; l < Ll; l++) bbar += b2[l * Dd + d];
        bbar *= 0.25f;
        float acc[8];
        #pragma unroll
        for (int r = 0; r < 8; r++) acc[r] = 0.f;
        for (int o = 0; o < Ll * Hh; o++) {
            float w = W2[(size_t)o * Dd + d];
            #pragma unroll
            for (int r = 0; r < 8; r++)
                acc[r] = fmaf(hs[(halfr * 8 + r) * 256 + o], w, acc[r]);
        }
        #pragma unroll
        for (int r = 0; r < 8; r++)
            xl[(halfr * 8 + r) * 128 + d] = fmaf(acc[r], 0.25f, bbar);
    }
    __syncthreads();

    {
        int dcol = tid & 127;
        int half = tid >> 7;                 // 0 = src, 1 = tgt
        float acc[16];
        float binit = half ? bs1[dcol] : 0.f;
        #pragma unroll
        for (int r = 0; r < 16; r++) acc[r] = binit;
        const float* ws = Ws1 + (size_t)half * Dd * Dd + dcol;
        for (int dd = 0; dd < Dd; dd++) {
            float w = ws[dd * Dd];
            #pragma unroll
            for (int r = 0; r < 16; r++)
                acc[r] = fmaf(xl[r * 128 + dd], w, acc[r]);
        }
        float* dst = half ? g_tgt : g_src;
        #pragma unroll
        for (int r = 0; r < 16; r++)
            dst[(size_t)(bn0 + r) * Dd + dcol] = acc[r];
    }
}

// ---------------- stage 2: pairwise scorer (packed f32x2) ----------------
__device__ __forceinline__ ull pk2(float x) {
    ull r;
    asm("mov.b64 %0, {%1, %1};" : "=l"(r) : "f"(x));
    return r;
}

__device__ __forceinline__ void pstep(ull& acc, ull t2, ull s2, ull w2) {
    asm("{\n\t"
        ".reg .b64 t;\n\t"
        ".reg .f32 lo, hi;\n\t"
        "add.rn.f32x2 t, %1, %2;\n\t"
        "mov.b64 {lo, hi}, t;\n\t"
        "max.f32 lo, lo, 0f00000000;\n\t"
        "max.f32 hi, hi, 0f00000000;\n\t"
        "mov.b64 t, {lo, hi};\n\t"
        "fma.rn.f32x2 %0, t, %3, %0;\n\t"
        "}"
        : "+l"(acc) : "l"(t2), "l"(s2), "l"(w2));
}

__global__ __launch_bounds__(128) void k_score(
    const float* __restrict__ Ws2, const float* __restrict__ bs2)
{
    __shared__ float st [32][132];   // [i][d]
    __shared__ float ttT[128][36];   // [d][j]
    __shared__ float w4[128];

    int b  = blockIdx.z;
    int i0 = blockIdx.y * 32, j0 = blockIdx.x * 32;
    int tx = threadIdx.x, ty = threadIdx.y;
    int tid = ty * 4 + tx;

    #pragma unroll
    for (int it = 0; it < 8; it++) {
        int e = tid + it * 128;
        int r = e >> 5, c4 = (e & 31) * 4;
        *(float4*)&st[r][c4] =
            *(const float4*)&g_src[(size_t)(b * Nn + i0 + r) * Dd + c4];
    }
    #pragma unroll
    for (int it = 0; it < 2; it++) {
        int e  = tid + it * 128;
        int j4 = (e & 7) * 4, d4 = (e >> 3) * 4;
        const float* base = g_tgt + (size_t)(b * Nn + j0 + j4) * Dd + d4;
        float4 r0 = *(const float4*)(base);
        float4 r1 = *(const float4*)(base + Dd);
        float4 r2 = *(const float4*)(base + 2 * Dd);
        float4 r3 = *(const float4*)(base + 3 * Dd);
        *(float4*)&ttT[d4 + 0][j4] = make_float4(r0.x, r1.x, r2.x, r3.x);
        *(float4*)&ttT[d4 + 1][j4] = make_float4(r0.y, r1.y, r2.y, r3.y);
        *(float4*)&ttT[d4 + 2][j4] = make_float4(r0.z, r1.z, r2.z, r3.z);
        *(float4*)&ttT[d4 + 3][j4] = make_float4(r0.w, r1.w, r2.w, r3.w);
    }
    w4[tid] = Ws2[tid];
    __syncthreads();

    int ti = ty;
    int jb = tx * 8;
    ull acc01 = 0, acc23 = 0, acc45 = 0, acc67 = 0;

    #pragma unroll 4
    for (int d = 0; d < Dd; d += 4) {
        float4 sv = *(const float4*)&st[ti][d];
        float4 wv = *(const float4*)&w4[d];
        float svv[4] = {sv.x, sv.y, sv.z, sv.w};
        float wvv[4] = {wv.x, wv.y, wv.z, wv.w};
        #pragma unroll
        for (int q = 0; q < 4; q++) {
            ulonglong2 ta = *(const ulonglong2*)&ttT[d + q][jb];
            ulonglong2 tb = *(const ulonglong2*)&ttT[d + q][jb + 4];
            ull s2 = pk2(svv[q]);
            ull w2 = pk2(wvv[q]);
            pstep(acc01, ta.x, s2, w2);
            pstep(acc23, ta.y, s2, w2);
            pstep(acc45, tb.x, s2, w2);
            pstep(acc67, tb.y, s2, w2);
        }
    }

    float a[8];
    asm("mov.b64 {%0, %1}, %2;" : "=f"(a[0]), "=f"(a[1]) : "l"(acc01));
    asm("mov.b64 {%0, %1}, %2;" : "=f"(a[2]), "=f"(a[3]) : "l"(acc23));
    asm("mov.b64 {%0, %1}, %2;" : "=f"(a[4]), "=f"(a[5]) : "l"(acc45));
    asm("mov.b64 {%0, %1}, %2;" : "=f"(a[6]), "=f"(a[7]) : "l"(acc67));

    float bz = bs2[0];
    int i = i0 + ti;
    float o[8];
    #pragma unroll
    for (int jj = 0; jj < 8; jj++) {
        int j = j0 + jb + jj;
        float sc = 1.f / (1.f + __expf(-(a[jj] + bz)));
        o[jj] = (sc > 0.1f && i != j) ? sc : 0.f;
    }
    float* dst = g_adj + ((size_t)b * Nn + i) * Nn + j0 + jb;
    *(float4*)(dst)     = make_float4(o[0], o[1], o[2], o[3]);
    *(float4*)(dst + 4) = make_float4(o[4], o[5], o[6], o[7]);
}

// ---------------- stage 3/4: TF32 GEMMs, split-K=2, register double-buffer --
// PHASE=0: p_kh = adj[:, kslice] @ adj[kslice, :]
// PHASE=1: q_kh = (p0+p1)[:, kslice] @ adj[kslice, :]   (A summed during load)
#define TM 64
#define TN 64
#define TK 32
#define KH 256
#define ASTR 36
#define BSTR 72

__device__ __forceinline__ void mma_tf32(float* d, const unsigned* a,
                                         const unsigned* b, const float* c) {
    asm volatile(
        "mma.sync.aligned.m16n8k8.row.col.f32.tf32.tf32.f32 "
        "{%0,%1,%2,%3}, {%4,%5,%6,%7}, {%8,%9}, {%10,%11,%12,%13};\n"
        : "=f"(d[0]), "=f"(d[1]), "=f"(d[2]), "=f"(d[3])
        : "r"(a[0]), "r"(a[1]), "r"(a[2]), "r"(a[3]),
          "r"(b[0]), "r"(b[1]),
          "f"(c[0]), "f"(c[1]), "f"(c[2]), "f"(c[3]));
}

template <int PHASE>
__global__ __launch_bounds__(128) void k_mma()
{
    int z  = blockIdx.z;
    int b  = z >> 1;
    int kh = z & 1;
    int kbase = kh * KH;

    const float* A1 = (PHASE ? g_p0 : g_adj) + (size_t)b * Nn * Nn;
    const float* A2 = g_p1 + (size_t)b * Nn * Nn;   // used only if PHASE
    const float* Bp = g_adj + (size_t)b * Nn * Nn;
    float* Ob = (PHASE ? (kh ? g_q1 : g_q0) : (kh ? g_p1 : g_p0))
                + (size_t)b * Nn * Nn;

    __shared__ float As[2][TM * ASTR];
    __shared__ float Bs[2][TK * BSTR];

    int tid  = threadIdx.x;
    int m0   = blockIdx.y * TM, n0 = blockIdx.x * TN;
    int warpId = tid >> 5, lane = tid & 31;
    int wm  = (warpId & 1) * 32;
    int wn  = (warpId >> 1) * 32;
    int gid = lane >> 2, tig = lane & 3;

    int arow = tid >> 3, ac4 = (tid & 7) * 4;     // A rows arow + p*16
    int brow = tid >> 4, bc4 = (tid & 15) * 4;    // B rows brow + p*8

    const float* agp  = A1 + (size_t)(m0 + arow) * Nn + kbase + ac4;
    const float* agp2 = A2 + (size_t)(m0 + arow) * Nn + kbase + ac4;
    const float* bgp  = Bp + (size_t)(kbase + brow) * Nn + n0 + bc4;

    float4 ra[4], rb[4];
    #pragma unroll
    for (int p = 0; p < 4; p++) {
        ra[p] = *(const float4*)(agp + (size_t)p * 16 * Nn);
        if (PHASE) {
            float4 e = *(const float4*)(agp2 + (size_t)p * 16 * Nn);
            ra[p].x += e.x; ra[p].y += e.y; ra[p].z += e.z; ra[p].w += e.w;
        }
        rb[p] = *(const float4*)(bgp + (size_t)p * 8 * Nn);
    }
    #pragma unroll
    for (int p = 0; p < 4; p++) {
        *(float4*)(As[0] + (arow + p * 16) * ASTR + ac4) = ra[p];
        *(float4*)(Bs[0] + (brow + p * 8) * BSTR + bc4)  = rb[p];
    }
    __syncthreads();

    float acc[2][4][4];
    #pragma unroll
    for (int i = 0; i < 2; i++)
        #pragma unroll
        for (int j = 0; j < 4; j++)
            #pragma unroll
            for (int r = 0; r < 4; r++) acc[i][j][r] = 0.f;

    const int NT = KH / TK;
    #pragma unroll 1
    for (int kt = 0; kt < NT; kt++) {
        int cur = kt & 1;
        if (kt + 1 < NT) {                        // prefetch next panel
            int k0 = (kt + 1) * TK;
            #pragma unroll
            for (int p = 0; p < 4; p++) {
                ra[p] = *(const float4*)(agp + k0 + (size_t)p * 16 * Nn);
                if (PHASE) {
                    float4 e = *(const float4*)(agp2 + k0 + (size_t)p * 16 * Nn);
                    ra[p].x += e.x; ra[p].y += e.y; ra[p].z += e.z; ra[p].w += e.w;
                }
                rb[p] = *(const float4*)(bgp + (size_t)k0 * Nn + (size_t)p * 8 * Nn);
            }
        }

        const float* Ac = As[cur];
        const float* Bc = Bs[cur];
        #pragma unroll
        for (int ks = 0; ks < 4; ks++) {
            int kb = ks * 8;
            unsigned af[2][4], bf[4][2];
            #pragma unroll
            for (int mt = 0; mt < 2; mt++) {
                int r0 = wm + mt * 16 + gid;
                af[mt][0] = __float_as_uint(Ac[r0 * ASTR + kb + tig]);
                af[mt][1] = __float_as_uint(Ac[(r0 + 8) * ASTR + kb + tig]);
                af[mt][2] = __float_as_uint(Ac[r0 * ASTR + kb + tig + 4]);
                af[mt][3] = __float_as_uint(Ac[(r0 + 8) * ASTR + kb + tig + 4]);
            }
            #pragma unroll
            for (int nt = 0; nt < 4; nt++) {
                int c0 = wn + nt * 8 + gid;
                bf[nt][0] = __float_as_uint(Bc[(kb + tig) * BSTR + c0]);
                bf[nt][1] = __float_as_uint(Bc[(kb + tig + 4) * BSTR + c0]);
            }
            #pragma unroll
            for (int mt = 0; mt < 2; mt++)
                #pragma unroll
                for (int nt = 0; nt < 4; nt++)
                    mma_tf32(acc[mt][nt], af[mt], bf[nt], acc[mt][nt]);
        }

        if (kt + 1 < NT) {
            int nxt = cur ^ 1;
            #pragma unroll
            for (int p = 0; p < 4; p++) {
                *(float4*)(As[nxt] + (arow + p * 16) * ASTR + ac4) = ra[p];
                *(float4*)(Bs[nxt] + (brow + p * 8) * BSTR + bc4)  = rb[p];
            }
        }
        __syncthreads();
    }

    #pragma unroll
    for (int mt = 0; mt < 2; mt++) {
        #pragma unroll
        for (int nt = 0; nt < 4; nt++) {
            int row = m0 + wm + mt * 16 + gid;
            int col = n0 + wn + nt * 8 + 2 * tig;
            #pragma unroll
            for (int h = 0; h < 2; h++) {
                int r = row + h * 8;
                *(float2*)(Ob + (size_t)r * Nn + col) =
                    make_float2(acc[mt][nt][2 * h + 0], acc[mt][nt][2 * h + 1]);
            }
        }
    }
}

// ---------------- stage 5: combine + per-batch max ----------------
__global__ __launch_bounds__(256) void k_enhance(float* __restrict__ out)
{
    __shared__ float wmax[8];
    int idx = blockIdx.x * 256 + threadIdx.x;     // over B*N*N/4 float4
    int b = idx >> 16;

    float4 a  = ((const float4*)g_adj)[idx];
    float4 p0 = ((const float4*)g_p0)[idx];
    float4 p1 = ((const float4*)g_p1)[idx];
    float4 q0 = ((const float4*)g_q0)[idx];
    float4 q1 = ((const float4*)g_q1)[idx];

    float4 e;
    e.x = a.x + 0.5f * (p0.x + p1.x) + 0.25f * (q0.x + q1.x);
    e.y = a.y + 0.5f * (p0.y + p1.y) + 0.25f * (q0.y + q1.y);
    e.z = a.z + 0.5f * (p0.z + p1.z) + 0.25f * (q0.z + q1.z);
    e.w = a.w + 0.5f * (p0.w + p1.w) + 0.25f * (q0.w + q1.w);
    ((float4*)out)[idx] = e;

    float lmax = fmaxf(fmaxf(e.x, e.y), fmaxf(e.z, e.w));
    #pragma unroll
    for (int s = 16; s > 0; s >>= 1)
        lmax = fmaxf(lmax, __shfl_xor_sync(0xFFFFFFFFu, lmax, s));
    int warpId = threadIdx.x >> 5, lane = threadIdx.x & 31;
    if (lane == 0) wmax[warpId] = lmax;
    __syncthreads();
    if (threadIdx.x == 0) {
        float m = wmax[0];
        #pragma unroll
        for (int i = 1; i < 8; i++) m = fmaxf(m, wmax[i]);
        atomicMax(&g_maxbits[b], __float_as_uint(m));
    }
}

// ---------------- stage 6: normalize (float4) ----------------
__global__ void k_norm(float* __restrict__ out)
{
    int idx = blockIdx.x * 256 + threadIdx.x;
    int b = idx >> 16;
    float mx = __uint_as_float(g_maxbits[b]);
    float inv = 1.f / (mx + 1e-8f);
    float4 v = ((const float4*)out)[idx];
    v.x *= inv; v.y *= inv; v.z *= inv; v.w *= inv;
    ((float4*)out)[idx] = v;
}

// ---------------- launch ----------------
extern "C" void kernel_launch(void* const* d_in, const int* in_sizes, int n_in,
                              void* d_out, int out_size)
{
    const float* x   = (const float*)d_in[0];
    const float* W1  = (const float*)d_in[1];
    const float* b1  = (const float*)d_in[2];
    const float* W2  = (const float*)d_in[3];
    const float* b2  = (const float*)d_in[4];
    const float* Ws1 = (const float*)d_in[5];
    const float* bs1 = (const float*)d_in[6];
    const float* Ws2 = (const float*)d_in[7];
    const float* bs2 = (const float*)d_in[8];
    float* out = (float*)d_out;

    k_encode<<<(Bb * Nn) / 16, 256>>>(x, W1, b1, W2, b2, Ws1, bs1);
    k_score<<<dim3(Nn / 32, Nn / 32, Bb), dim3(4, 32)>>>(Ws2, bs2);
    k_mma<0><<<dim3(Nn / TN, Nn / TM, Bb * 2), 128>>>();
    k_mma<1><<<dim3(Nn / TN, Nn / TM, Bb * 2), 128>>>();
    k_enhance<<<(Bb * Nn * Nn) / 1024, 256>>>(out);
    k_norm<<<(Bb * Nn * Nn) / 1024, 256>>>(out);
}

// round 15
// speedup vs baseline: 1.1369x; 1.1142x over previous
#include <cuda_runtime.h>

#define Bb 4
#define Tt 12
#define Nn 512
#define Dd 128
#define Ll 4
#define Hh 64

typedef unsigned long long ull;

// ---------------- scratch (no allocation allowed) ----------------
__device__ float g_src[Bb * Nn * Dd];     // src_proj
__device__ float g_tgt[Bb * Nn * Dd];     // tgt_proj + bs1 folded in
__device__ float g_adj[Bb * Nn * Nn];     // thresholded adjacency
__device__ float g_p0[Bb * Nn * Nn];      // a2 partial (k-half 0)
__device__ float g_p1[Bb * Nn * Nn];      // a2 partial (k-half 1)
__device__ float g_q0[Bb * Nn * Nn];      // a3 partial (k-half 0)
__device__ float g_q1[Bb * Nn * Nn];      // a3 partial (k-half 1)
__device__ unsigned g_maxbits[Bb];        // per-batch max (float bits, all >= 0)

// ---------------- packed f32x2 helpers ----------------
__device__ __forceinline__ ull pkw(float lo, float hi) {
    ull r; asm("mov.b64 %0, {%1, %2};" : "=l"(r) : "f"(lo), "f"(hi)); return r;
}
__device__ __forceinline__ void pfma(ull& acc, ull x, ull w) {
    asm("fma.rn.f32x2 %0, %1, %2, %0;" : "+l"(acc) : "l"(x), "l"(w));
}
__device__ __forceinline__ float unpsum(ull a) {
    float lo, hi; asm("mov.b64 {%0, %1}, %2;" : "=f"(lo), "=f"(hi) : "l"(a));
    return lo + hi;
}
__device__ __forceinline__ ull pk2(float x) {
    ull r; asm("mov.b64 %0, {%1, %1};" : "=l"(r) : "f"(x)); return r;
}

// ---------------- stage 1: lag encoders + mean + projections ----------------
// f32x2 accumulation, float4 broadcast LDS, packed weights
__global__ __launch_bounds__(256) void k_encode(
    const float* __restrict__ x,
    const float* __restrict__ W1, const float* __restrict__ b1,
    const float* __restrict__ W2, const float* __restrict__ b2,
    const float* __restrict__ Ws1, const float* __restrict__ bs1)
{
    __shared__ float xl[16 * 512];   // [(r*4+l)*128 + d]; later reused as agg[r*128+d]
    __shared__ float hs[16 * 256];   // [r*256 + l*64 + j]

    int tid = threadIdx.x;
    if (blockIdx.x == 0 && tid < Bb) g_maxbits[tid] = 0u;   // folded k_init

    int bn0 = blockIdx.x * 16;           // first global row (b*N + n)
    int b   = bn0 >> 9;
    int n0  = bn0 & (Nn - 1);

    #pragma unroll
    for (int i = 0; i < 32; i++) {
        int e  = tid + i * 256;
        int d  = e & 127;
        int rl = e >> 7;
        int r  = rl >> 2, l = rl & 3;
        xl[e] = x[(((b * Tt) + (Tt - 1 - l)) * Nn + (n0 + r)) * Dd + d];
    }
    __syncthreads();

    // stage A: h[r][l][j] = relu(b1 + sum_d xl * W1)
    {
        int l = tid >> 6, j = tid & 63;
        ull acc2[16];
        #pragma unroll
        for (int r = 0; r < 16; r++) acc2[r] = 0;
        const float* w1p = W1 + (size_t)l * Dd * Hh + j;
        for (int d = 0; d < Dd; d += 4) {
            float w0 = w1p[(d + 0) * Hh], wa = w1p[(d + 1) * Hh];
            float wb = w1p[(d + 2) * Hh], wc = w1p[(d + 3) * Hh];
            ull w01 = pkw(w0, wa), w23 = pkw(wb, wc);
            #pragma unroll
            for (int r = 0; r < 16; r++) {
                ulonglong2 xv = *(const ulonglong2*)&xl[(r * 4 + l) * 128 + d];
                pfma(acc2[r], xv.x, w01);
                pfma(acc2[r], xv.y, w23);
            }
        }
        float bb = b1[l * Hh + j];
        #pragma unroll
        for (int r = 0; r < 16; r++)
            hs[r * 256 + tid] = fmaxf(unpsum(acc2[r]) + bb, 0.f);
    }
    __syncthreads();

    // stage B: agg[r][d] = 0.25*(sum_o hs*W2) + 0.25*sum_l b2
    {
        int d = tid & 127, halfr = tid >> 7;
        float bbar = 0.f;
        #pragma unroll
        for (int l = 0; l < Ll; l++) bbar += b2[l * Dd + d];
        bbar *= 0.25f;
        ull acc2[8];
        #pragma unroll
        for (int r = 0; r < 8; r++) acc2[r] = 0;
        for (int o = 0; o < Ll * Hh; o += 4) {
            float w0 = W2[(size_t)(o + 0) * Dd + d], wa = W2[(size_t)(o + 1) * Dd + d];
            float wb = W2[(size_t)(o + 2) * Dd + d], wc = W2[(size_t)(o + 3) * Dd + d];
            ull w01 = pkw(w0, wa), w23 = pkw(wb, wc);
            #pragma unroll
            for (int r = 0; r < 8; r++) {
                ulonglong2 hv = *(const ulonglong2*)&hs[(halfr * 8 + r) * 256 + o];
                pfma(acc2[r], hv.x, w01);
                pfma(acc2[r], hv.y, w23);
            }
        }
        #pragma unroll
        for (int r = 0; r < 8; r++)
            xl[(halfr * 8 + r) * 128 + d] = fmaf(unpsum(acc2[r]), 0.25f, bbar);
    }
    __syncthreads();

    // stage C: src/tgt projections
    {
        int dcol = tid & 127;
        int half = tid >> 7;                 // 0 = src, 1 = tgt
        ull acc2[16];
        #pragma unroll
        for (int r = 0; r < 16; r++) acc2[r] = 0;
        const float* ws = Ws1 + (size_t)half * Dd * Dd + dcol;
        for (int dd = 0; dd < Dd; dd += 4) {
            float w0 = ws[(dd + 0) * Dd], wa = ws[(dd + 1) * Dd];
            float wb = ws[(dd + 2) * Dd], wc = ws[(dd + 3) * Dd];
            ull w01 = pkw(w0, wa), w23 = pkw(wb, wc);
            #pragma unroll
            for (int r = 0; r < 16; r++) {
                ulonglong2 xv = *(const ulonglong2*)&xl[r * 128 + dd];
                pfma(acc2[r], xv.x, w01);
                pfma(acc2[r], xv.y, w23);
            }
        }
        float binit = half ? bs1[dcol] : 0.f;
        float* dst = half ? g_tgt : g_src;
        #pragma unroll
        for (int r = 0; r < 16; r++)
            dst[(size_t)(bn0 + r) * Dd + dcol] = unpsum(acc2[r]) + binit;
    }
}

// ---------------- stage 2: pairwise scorer (packed f32x2) ----------------
__device__ __forceinline__ void pstep(ull& acc, ull t2, ull s2, ull w2) {
    asm("{\n\t"
        ".reg .b64 t;\n\t"
        ".reg .f32 lo, hi;\n\t"
        "add.rn.f32x2 t, %1, %2;\n\t"
        "mov.b64 {lo, hi}, t;\n\t"
        "max.f32 lo, lo, 0f00000000;\n\t"
        "max.f32 hi, hi, 0f00000000;\n\t"
        "mov.b64 t, {lo, hi};\n\t"
        "fma.rn.f32x2 %0, t, %3, %0;\n\t"
        "}"
        : "+l"(acc) : "l"(t2), "l"(s2), "l"(w2));
}

__global__ __launch_bounds__(128) void k_score(
    const float* __restrict__ Ws2, const float* __restrict__ bs2)
{
    __shared__ float st [32][132];   // [i][d]
    __shared__ float ttT[128][36];   // [d][j]
    __shared__ float w4[128];

    int b  = blockIdx.z;
    int i0 = blockIdx.y * 32, j0 = blockIdx.x * 32;
    int tx = threadIdx.x, ty = threadIdx.y;
    int tid = ty * 4 + tx;

    #pragma unroll
    for (int it = 0; it < 8; it++) {
        int e = tid + it * 128;
        int r = e >> 5, c4 = (e & 31) * 4;
        *(float4*)&st[r][c4] =
            *(const float4*)&g_src[(size_t)(b * Nn + i0 + r) * Dd + c4];
    }
    #pragma unroll
    for (int it = 0; it < 2; it++) {
        int e  = tid + it * 128;
        int j4 = (e & 7) * 4, d4 = (e >> 3) * 4;
        const float* base = g_tgt + (size_t)(b * Nn + j0 + j4) * Dd + d4;
        float4 r0 = *(const float4*)(base);
        float4 r1 = *(const float4*)(base + Dd);
        float4 r2 = *(const float4*)(base + 2 * Dd);
        float4 r3 = *(const float4*)(base + 3 * Dd);
        *(float4*)&ttT[d4 + 0][j4] = make_float4(r0.x, r1.x, r2.x, r3.x);
        *(float4*)&ttT[d4 + 1][j4] = make_float4(r0.y, r1.y, r2.y, r3.y);
        *(float4*)&ttT[d4 + 2][j4] = make_float4(r0.z, r1.z, r2.z, r3.z);
        *(float4*)&ttT[d4 + 3][j4] = make_float4(r0.w, r1.w, r2.w, r3.w);
    }
    w4[tid] = Ws2[tid];
    __syncthreads();

    int ti = ty;
    int jb = tx * 8;
    ull acc01 = 0, acc23 = 0, acc45 = 0, acc67 = 0;

    #pragma unroll 4
    for (int d = 0; d < Dd; d += 4) {
        float4 sv = *(const float4*)&st[ti][d];
        float4 wv = *(const float4*)&w4[d];
        float svv[4] = {sv.x, sv.y, sv.z, sv.w};
        float wvv[4] = {wv.x, wv.y, wv.z, wv.w};
        #pragma unroll
        for (int q = 0; q < 4; q++) {
            ulonglong2 ta = *(const ulonglong2*)&ttT[d + q][jb];
            ulonglong2 tb = *(const ulonglong2*)&ttT[d + q][jb + 4];
            ull s2 = pk2(svv[q]);
            ull w2 = pk2(wvv[q]);
            pstep(acc01, ta.x, s2, w2);
            pstep(acc23, ta.y, s2, w2);
            pstep(acc45, tb.x, s2, w2);
            pstep(acc67, tb.y, s2, w2);
        }
    }

    float a[8];
    asm("mov.b64 {%0, %1}, %2;" : "=f"(a[0]), "=f"(a[1]) : "l"(acc01));
    asm("mov.b64 {%0, %1}, %2;" : "=f"(a[2]), "=f"(a[3]) : "l"(acc23));
    asm("mov.b64 {%0, %1}, %2;" : "=f"(a[4]), "=f"(a[5]) : "l"(acc45));
    asm("mov.b64 {%0, %1}, %2;" : "=f"(a[6]), "=f"(a[7]) : "l"(acc67));

    float bz = bs2[0];
    int i = i0 + ti;
    float o[8];
    #pragma unroll
    for (int jj = 0; jj < 8; jj++) {
        int j = j0 + jb + jj;
        float sc = 1.f / (1.f + __expf(-(a[jj] + bz)));
        o[jj] = (sc > 0.1f && i != j) ? sc : 0.f;
    }
    float* dst = g_adj + ((size_t)b * Nn + i) * Nn + j0 + jb;
    *(float4*)(dst)     = make_float4(o[0], o[1], o[2], o[3]);
    *(float4*)(dst + 4) = make_float4(o[4], o[5], o[6], o[7]);
}

// ---------------- stage 3/4: TF32 GEMMs, split-K=2, register double-buffer --
// PHASE=0: p_kh = adj[:, kslice] @ adj[kslice, :]
// PHASE=1: q_kh = (p0+p1)[:, kslice] @ adj[kslice, :]   (A summed during load)
#define TM 64
#define TN 64
#define TK 32
#define KH 256
#define ASTR 36
#define BSTR 72

__device__ __forceinline__ void mma_tf32(float* d, const unsigned* a,
                                         const unsigned* b, const float* c) {
    asm volatile(
        "mma.sync.aligned.m16n8k8.row.col.f32.tf32.tf32.f32 "
        "{%0,%1,%2,%3}, {%4,%5,%6,%7}, {%8,%9}, {%10,%11,%12,%13};\n"
        : "=f"(d[0]), "=f"(d[1]), "=f"(d[2]), "=f"(d[3])
        : "r"(a[0]), "r"(a[1]), "r"(a[2]), "r"(a[3]),
          "r"(b[0]), "r"(b[1]),
          "f"(c[0]), "f"(c[1]), "f"(c[2]), "f"(c[3]));
}

template <int PHASE>
__global__ __launch_bounds__(128) void k_mma()
{
    int z  = blockIdx.z;
    int b  = z >> 1;
    int kh = z & 1;
    int kbase = kh * KH;

    const float* A1 = (PHASE ? g_p0 : g_adj) + (size_t)b * Nn * Nn;
    const float* A2 = g_p1 + (size_t)b * Nn * Nn;   // used only if PHASE
    const float* Bp = g_adj + (size_t)b * Nn * Nn;
    float* Ob = (PHASE ? (kh ? g_q1 : g_q0) : (kh ? g_p1 : g_p0))
                + (size_t)b * Nn * Nn;

    __shared__ float As[2][TM * ASTR];
    __shared__ float Bs[2][TK * BSTR];

    int tid  = threadIdx.x;
    int m0   = blockIdx.y * TM, n0 = blockIdx.x * TN;
    int warpId = tid >> 5, lane = tid & 31;
    int wm  = (warpId & 1) * 32;
    int wn  = (warpId >> 1) * 32;
    int gid = lane >> 2, tig = lane & 3;

    int arow = tid >> 3, ac4 = (tid & 7) * 4;     // A rows arow + p*16
    int brow = tid >> 4, bc4 = (tid & 15) * 4;    // B rows brow + p*8

    const float* agp  = A1 + (size_t)(m0 + arow) * Nn + kbase + ac4;
    const float* agp2 = A2 + (size_t)(m0 + arow) * Nn + kbase + ac4;
    const float* bgp  = Bp + (size_t)(kbase + brow) * Nn + n0 + bc4;

    float4 ra[4], rb[4];
    #pragma unroll
    for (int p = 0; p < 4; p++) {
        ra[p] = *(const float4*)(agp + (size_t)p * 16 * Nn);
        if (PHASE) {
            float4 e = *(const float4*)(agp2 + (size_t)p * 16 * Nn);
            ra[p].x += e.x; ra[p].y += e.y; ra[p].z += e.z; ra[p].w += e.w;
        }
        rb[p] = *(const float4*)(bgp + (size_t)p * 8 * Nn);
    }
    #pragma unroll
    for (int p = 0; p < 4; p++) {
        *(float4*)(As[0] + (arow + p * 16) * ASTR + ac4) = ra[p];
        *(float4*)(Bs[0] + (brow + p * 8) * BSTR + bc4)  = rb[p];
    }
    __syncthreads();

    float acc[2][4][4];
    #pragma unroll
    for (int i = 0; i < 2; i++)
        #pragma unroll
        for (int j = 0; j < 4; j++)
            #pragma unroll
            for (int r = 0; r < 4; r++) acc[i][j][r] = 0.f;

    const int NT = KH / TK;
    #pragma unroll 1
    for (int kt = 0; kt < NT; kt++) {
        int cur = kt & 1;
        if (kt + 1 < NT) {                        // prefetch next panel
            int k0 = (kt + 1) * TK;
            #pragma unroll
            for (int p = 0; p < 4; p++) {
                ra[p] = *(const float4*)(agp + k0 + (size_t)p * 16 * Nn);
                if (PHASE) {
                    float4 e = *(const float4*)(agp2 + k0 + (size_t)p * 16 * Nn);
                    ra[p].x += e.x; ra[p].y += e.y; ra[p].z += e.z; ra[p].w += e.w;
                }
                rb[p] = *(const float4*)(bgp + (size_t)k0 * Nn + (size_t)p * 8 * Nn);
            }
        }

        const float* Ac = As[cur];
        const float* Bc = Bs[cur];
        #pragma unroll
        for (int ks = 0; ks < 4; ks++) {
            int kb = ks * 8;
            unsigned af[2][4], bf[4][2];
            #pragma unroll
            for (int mt = 0; mt < 2; mt++) {
                int r0 = wm + mt * 16 + gid;
                af[mt][0] = __float_as_uint(Ac[r0 * ASTR + kb + tig]);
                af[mt][1] = __float_as_uint(Ac[(r0 + 8) * ASTR + kb + tig]);
                af[mt][2] = __float_as_uint(Ac[r0 * ASTR + kb + tig + 4]);
                af[mt][3] = __float_as_uint(Ac[(r0 + 8) * ASTR + kb + tig + 4]);
            }
            #pragma unroll
            for (int nt = 0; nt < 4; nt++) {
                int c0 = wn + nt * 8 + gid;
                bf[nt][0] = __float_as_uint(Bc[(kb + tig) * BSTR + c0]);
                bf[nt][1] = __float_as_uint(Bc[(kb + tig + 4) * BSTR + c0]);
            }
            #pragma unroll
            for (int mt = 0; mt < 2; mt++)
                #pragma unroll
                for (int nt = 0; nt < 4; nt++)
                    mma_tf32(acc[mt][nt], af[mt], bf[nt], acc[mt][nt]);
        }

        if (kt + 1 < NT) {
            int nxt = cur ^ 1;
            #pragma unroll
            for (int p = 0; p < 4; p++) {
                *(float4*)(As[nxt] + (arow + p * 16) * ASTR + ac4) = ra[p];
                *(float4*)(Bs[nxt] + (brow + p * 8) * BSTR + bc4)  = rb[p];
            }
        }
        __syncthreads();
    }

    #pragma unroll
    for (int mt = 0; mt < 2; mt++) {
        #pragma unroll
        for (int nt = 0; nt < 4; nt++) {
            int row = m0 + wm + mt * 16 + gid;
            int col = n0 + wn + nt * 8 + 2 * tig;
            #pragma unroll
            for (int h = 0; h < 2; h++) {
                int r = row + h * 8;
                *(float2*)(Ob + (size_t)r * Nn + col) =
                    make_float2(acc[mt][nt][2 * h + 0], acc[mt][nt][2 * h + 1]);
            }
        }
    }
}

// ---------------- stage 5: combine + per-batch max ----------------
__global__ __launch_bounds__(256) void k_enhance(float* __restrict__ out)
{
    __shared__ float wmax[8];
    int idx = blockIdx.x * 256 + threadIdx.x;     // over B*N*N/4 float4
    int b = idx >> 16;

    float4 a  = ((const float4*)g_adj)[idx];
    float4 p0 = ((const float4*)g_p0)[idx];
    float4 p1 = ((const float4*)g_p1)[idx];
    float4 q0 = ((const float4*)g_q0)[idx];
    float4 q1 = ((const float4*)g_q1)[idx];

    float4 e;
    e.x = a.x + 0.5f * (p0.x + p1.x) + 0.25f * (q0.x + q1.x);
    e.y = a.y + 0.5f * (p0.y + p1.y) + 0.25f * (q0.y + q1.y);
    e.z = a.z + 0.5f * (p0.z + p1.z) + 0.25f * (q0.z + q1.z);
    e.w = a.w + 0.5f * (p0.w + p1.w) + 0.25f * (q0.w + q1.w);
    ((float4*)out)[idx] = e;

    float lmax = fmaxf(fmaxf(e.x, e.y), fmaxf(e.z, e.w));
    #pragma unroll
    for (int s = 16; s > 0; s >>= 1)
        lmax = fmaxf(lmax, __shfl_xor_sync(0xFFFFFFFFu, lmax, s));
    int warpId = threadIdx.x >> 5, lane = threadIdx.x & 31;
    if (lane == 0) wmax[warpId] = lmax;
    __syncthreads();
    if (threadIdx.x == 0) {
        float m = wmax[0];
        #pragma unroll
        for (int i = 1; i < 8; i++) m = fmaxf(m, wmax[i]);
        atomicMax(&g_maxbits[b], __float_as_uint(m));
    }
}

// ---------------- stage 6: normalize (float4) ----------------
__global__ void k_norm(float* __restrict__ out)
{
    int idx = blockIdx.x * 256 + threadIdx.x;
    int b = idx >> 16;
    float mx = __uint_as_float(g_maxbits[b]);
    float inv = 1.f / (mx + 1e-8f);
    float4 v = ((const float4*)out)[idx];
    v.x *= inv; v.y *= inv; v.z *= inv; v.w *= inv;
    ((float4*)out)[idx] = v;
}

// ---------------- launch ----------------
extern "C" void kernel_launch(void* const* d_in, const int* in_sizes, int n_in,
                              void* d_out, int out_size)
{
    const float* x   = (const float*)d_in[0];
    const float* W1  = (const float*)d_in[1];
    const float* b1  = (const float*)d_in[2];
    const float* W2  = (const float*)d_in[3];
    const float* b2  = (const float*)d_in[4];
    const float* Ws1 = (const float*)d_in[5];
    const float* bs1 = (const float*)d_in[6];
    const float* Ws2 = (const float*)d_in[7];
    const float* bs2 = (const float*)d_in[8];
    float* out = (float*)d_out;

    k_encode<<<(Bb * Nn) / 16, 256>>>(x, W1, b1, W2, b2, Ws1, bs1);
    k_score<<<dim3(Nn / 32, Nn / 32, Bb), dim3(4, 32)>>>(Ws2, bs2);
    k_mma<0><<<dim3(Nn / TN, Nn / TM, Bb * 2), 128>>>();
    k_mma<1><<<dim3(Nn / TN, Nn / TM, Bb * 2), 128>>>();
    k_enhance<<<(Bb * Nn * Nn) / 1024, 256>>>(out);
    k_norm<<<(Bb * Nn * Nn) / 1024, 256>>>(out);
}